// round 1
// baseline (speedup 1.0000x reference)
#include <cuda_runtime.h>
#include <math.h>

#define B_   64
#define T_   2000
#define E_   512
#define D_   1024
#define A_   128
#define KS_  31
#define PAD_ 15

#define TTILE   128           // t per block tile
#define KCH     64            // K elements per chunk
#define NCHUNKS 9             // chunk 0 = conv (im2col), 1..8 = memory K
#define NTILES  16            // ceil(2000/128)
#define CCHUNKS 16            // context split chunks (2000 = 16*125)

// ---- smem layout (bytes) ----
// sW64: 64 rows x 130 u64 (broadcast-packed weights, swizzled)  : 66560
// sM64: 64 rows x  66 u64 (t-pair-packed activations)           : 33792
// sAw : 2 x 160 floats                                          : 1280
// sSc : 2 x 128 floats                                          : 1024
#define OFF_W   0
#define OFF_M   66560
#define OFF_AW  100352
#define OFF_SC  101632
#define SMEM_BYTES 102656

// scratch (allocation-free rule: __device__ globals)
__device__ float g_pq[B_ * A_];
__device__ float g_scores[B_ * T_];
__device__ float g_part[B_ * CCHUNKS * E_];

__device__ __forceinline__ unsigned long long fpack2(float lo, float hi) {
    unsigned long long r;
    asm("mov.b64 %0, {%1, %2};" : "=l"(r) : "f"(lo), "f"(hi));
    return r;
}
__device__ __forceinline__ void fma2(unsigned long long& d,
                                     unsigned long long a,
                                     unsigned long long b) {
    asm("fma.rn.f32x2 %0, %1, %2, %0;" : "+l"(d) : "l"(a), "l"(b));
}
__device__ __forceinline__ float2 funpack2(unsigned long long x) {
    float2 f;
    asm("mov.b64 {%0, %1}, %2;" : "=f"(f.x), "=f"(f.y) : "l"(x));
    return f;
}
__device__ __forceinline__ int swzc(int c) {  // 16B-chunk XOR swizzle within a 64-chunk row
    return c ^ ((c >> 3) & 7);
}

// ---------------------------------------------------------------------------
// pq[b][a] = sum_d query[b][d] * Wq[a][d]
// ---------------------------------------------------------------------------
__global__ void pq_kernel(const float* __restrict__ query,
                          const float* __restrict__ Wq) {
    int b = blockIdx.x;
    int warp = threadIdx.x >> 5, lane = threadIdx.x & 31;
    const float* q = query + (size_t)b * D_;
    for (int a = warp; a < A_; a += 4) {
        const float* w = Wq + (size_t)a * D_;
        float s = 0.f;
        for (int k = lane; k < D_; k += 32) s += q[k] * w[k];
        #pragma unroll
        for (int off = 16; off; off >>= 1)
            s += __shfl_xor_sync(0xffffffffu, s, off);
        if (lane == 0) g_pq[b * A_ + a] = s;
    }
}

// ---------------------------------------------------------------------------
// Fused: pm GEMM + location conv (as extra K-chunk) + pq + tanh + v-dot
// Block tile: 128 t x 128 a, K = 512 (+64 conv). 256 threads.
// Thread tile: 4 t-pairs x 8 a, f32x2 packed along t.
// ---------------------------------------------------------------------------
__global__ void __launch_bounds__(256, 2)
scores_kernel(const float* __restrict__ memory,
              const float* __restrict__ aw,
              const float* __restrict__ Wm,
              const float* __restrict__ Wloc,
              const float* __restrict__ v) {
    extern __shared__ unsigned char smem[];
    unsigned long long* sW64 = (unsigned long long*)(smem + OFF_W);  // [64][130]
    unsigned long long* sM64 = (unsigned long long*)(smem + OFF_M);  // [64][66]
    float* sMf = (float*)sM64;                                       // stride 132
    float* sAw = (float*)(smem + OFF_AW);                            // [2][160]
    float* sSc = (float*)(smem + OFF_SC);                            // [2][128]

    const int tid = threadIdx.x;
    const int b = blockIdx.y;
    const int t0 = blockIdx.x * TTILE;

    const int warp = tid >> 5, lane = tid & 31;
    const int warpT = warp & 3, warpA = warp >> 2;   // 4 x 2 warp grid
    const int laneT = lane >> 3, laneA = lane & 7;   // 4 x 8 lane grid
    const int tpBase = warpT * 16 + laneT * 4;       // t-pair base (4 pairs)
    const int aBase = warpA * 64 + laneA * 8;        // a base (8 cols)

    // precomputed swizzled W row offsets (in u64) for this thread's 4 chunks
    int physW[4];
    #pragma unroll
    for (int j = 0; j < 4; ++j) {
        int c = (aBase >> 1) + j;
        physW[j] = swzc(c) << 1;
    }

    unsigned long long acc[4][8];
    #pragma unroll
    for (int p = 0; p < 4; ++p)
        #pragma unroll
        for (int j = 0; j < 8; ++j) acc[p][j] = 0ull;

    // attention-weights window [t0-15, t0+128+15)
    for (int i = tid; i < TTILE + 2 * PAD_; i += 256) {
        int tg = t0 - PAD_ + i;
        float c0 = 0.f, c1 = 0.f;
        if (tg >= 0 && tg < T_) {
            const float* p = aw + ((size_t)b * T_ + tg) * 2;
            c0 = p[0]; c1 = p[1];
        }
        sAw[i] = c0;
        sAw[160 + i] = c1;
    }
    __syncthreads();

    for (int chunk = 0; chunk < NCHUNKS; ++chunk) {
        if (chunk == 0) {
            // conv chunk: Wloc broadcast-packed, zero-padded j=62..63
            #pragma unroll
            for (int it = 0; it < 32; ++it) {
                int idx = it * 256 + tid;
                int jj = idx & 63, a = idx >> 6;
                float w = (jj < 62) ? Wloc[a * 62 + jj] : 0.f;
                int phys = (swzc(a >> 1) << 1) | (a & 1);
                sW64[jj * 130 + phys] = fpack2(w, w);
            }
            // im2col of aw window: sMf[j][t] = aw[b, t0+t+k-15, c], j=c*31+k
            #pragma unroll
            for (int it = 0; it < 32; ++it) {
                int idx = it * 256 + tid;
                int jj = idx >> 7, t = idx & 127;
                float x = 0.f;
                if (jj < 62) {
                    int c = (jj >= 31) ? 1 : 0;
                    int k = jj - c * 31;
                    x = sAw[c * 160 + t + k];
                }
                sMf[jj * 132 + t] = x;
            }
        } else {
            const int kbase = (chunk - 1) * KCH;
            // Wm chunk, broadcast-packed + swizzled
            #pragma unroll
            for (int it = 0; it < 8; ++it) {
                int idx = it * 256 + tid;
                int a = idx >> 4, q = idx & 15;
                float4 wv = *(const float4*)(Wm + (size_t)a * E_ + kbase + q * 4);
                int phys = (swzc(a >> 1) << 1) | (a & 1);
                sW64[(q * 4 + 0) * 130 + phys] = fpack2(wv.x, wv.x);
                sW64[(q * 4 + 1) * 130 + phys] = fpack2(wv.y, wv.y);
                sW64[(q * 4 + 2) * 130 + phys] = fpack2(wv.z, wv.z);
                sW64[(q * 4 + 3) * 130 + phys] = fpack2(wv.w, wv.w);
            }
            // memory tile, transposed to [kk][t] (padded stride kills store conflicts)
            #pragma unroll
            for (int it = 0; it < 8; ++it) {
                int idx = it * 256 + tid;
                int t = idx >> 4, q = idx & 15;
                float4 mv = make_float4(0.f, 0.f, 0.f, 0.f);
                int gt = t0 + t;
                if (gt < T_)
                    mv = *(const float4*)(memory + ((size_t)b * T_ + gt) * E_ + kbase + q * 4);
                sMf[(q * 4 + 0) * 132 + t] = mv.x;
                sMf[(q * 4 + 1) * 132 + t] = mv.y;
                sMf[(q * 4 + 2) * 132 + t] = mv.z;
                sMf[(q * 4 + 3) * 132 + t] = mv.w;
            }
        }
        __syncthreads();

        const unsigned long long* wrow = sW64;
        const unsigned long long* mrow = sM64 + tpBase;
        #pragma unroll 4
        for (int kk = 0; kk < KCH; ++kk) {
            ulonglong2 m01 = *(const ulonglong2*)(mrow);
            ulonglong2 m23 = *(const ulonglong2*)(mrow + 2);
            ulonglong2 w0 = *(const ulonglong2*)(wrow + physW[0]);
            ulonglong2 w1 = *(const ulonglong2*)(wrow + physW[1]);
            ulonglong2 w2 = *(const ulonglong2*)(wrow + physW[2]);
            ulonglong2 w3 = *(const ulonglong2*)(wrow + physW[3]);
            unsigned long long m[4] = {m01.x, m01.y, m23.x, m23.y};
            unsigned long long w[8] = {w0.x, w0.y, w1.x, w1.y,
                                       w2.x, w2.y, w3.x, w3.y};
            #pragma unroll
            for (int p = 0; p < 4; ++p)
                #pragma unroll
                for (int j = 0; j < 8; ++j) fma2(acc[p][j], m[p], w[j]);
            wrow += 130;
            mrow += 66;
        }
        __syncthreads();
    }

    // epilogue: + pq, tanh, dot v, reduce over a
    float pqv[8], vv[8];
    {
        const float4* pq4 = (const float4*)(g_pq + b * A_ + aBase);
        float4 q0 = pq4[0], q1 = pq4[1];
        pqv[0] = q0.x; pqv[1] = q0.y; pqv[2] = q0.z; pqv[3] = q0.w;
        pqv[4] = q1.x; pqv[5] = q1.y; pqv[6] = q1.z; pqv[7] = q1.w;
        const float4* v4 = (const float4*)(v + aBase);
        float4 v0 = v4[0], v1 = v4[1];
        vv[0] = v0.x; vv[1] = v0.y; vv[2] = v0.z; vv[3] = v0.w;
        vv[4] = v1.x; vv[5] = v1.y; vv[6] = v1.z; vv[7] = v1.w;
    }
    float sc[8];
    #pragma unroll
    for (int p = 0; p < 4; ++p) {
        float sLo = 0.f, sHi = 0.f;
        #pragma unroll
        for (int j = 0; j < 8; ++j) {
            float2 f = funpack2(acc[p][j]);
            sLo += vv[j] * tanhf(f.x + pqv[j]);
            sHi += vv[j] * tanhf(f.y + pqv[j]);
        }
        sc[2 * p] = sLo;
        sc[2 * p + 1] = sHi;
    }
    #pragma unroll
    for (int off = 1; off < 8; off <<= 1) {
        #pragma unroll
        for (int i = 0; i < 8; ++i)
            sc[i] += __shfl_xor_sync(0xffffffffu, sc[i], off);
    }
    if (laneA == 0) {
        #pragma unroll
        for (int i = 0; i < 8; ++i)
            sSc[warpA * 128 + tpBase * 2 + i] = sc[i];
    }
    __syncthreads();
    if (tid < 128) {
        int gt = t0 + tid;
        if (gt < T_) g_scores[b * T_ + gt] = sSc[tid] + sSc[128 + tid];
    }
}

// ---------------------------------------------------------------------------
// softmax over T per batch row
// ---------------------------------------------------------------------------
__global__ void softmax_kernel(float* __restrict__ align_out) {
    __shared__ float buf[T_];
    __shared__ float red[256];
    int b = blockIdx.x, tid = threadIdx.x;
    float mx = -1e30f;
    for (int t = tid; t < T_; t += 256) {
        float s = g_scores[b * T_ + t];
        buf[t] = s;
        mx = fmaxf(mx, s);
    }
    red[tid] = mx;
    __syncthreads();
    for (int off = 128; off; off >>= 1) {
        if (tid < off) red[tid] = fmaxf(red[tid], red[tid + off]);
        __syncthreads();
    }
    mx = red[0];
    __syncthreads();
    float sum = 0.f;
    for (int t = tid; t < T_; t += 256) {
        float e = __expf(buf[t] - mx);
        buf[t] = e;
        sum += e;
    }
    red[tid] = sum;
    __syncthreads();
    for (int off = 128; off; off >>= 1) {
        if (tid < off) red[tid] += red[tid + off];
        __syncthreads();
    }
    float inv = 1.f / red[0];
    for (int t = tid; t < T_; t += 256) align_out[b * T_ + t] = buf[t] * inv;
}

// ---------------------------------------------------------------------------
// context partials: split T into 16 chunks of 125 (deterministic, no atomics)
// ---------------------------------------------------------------------------
__global__ void ctx_part_kernel(const float* __restrict__ memory,
                                const float* __restrict__ aligns) {
    int chunk = blockIdx.x, b = blockIdx.y, tid = threadIdx.x;  // 128 threads
    __shared__ float sa[125];
    const float* al = aligns + (size_t)b * T_ + chunk * 125;
    for (int i = tid; i < 125; i += 128) sa[i] = al[i];
    __syncthreads();
    const float* mp = memory + ((size_t)b * T_ + (size_t)chunk * 125) * E_ + tid * 4;
    float4 acc = make_float4(0.f, 0.f, 0.f, 0.f);
    #pragma unroll 5
    for (int tt = 0; tt < 125; ++tt) {
        float a = sa[tt];
        float4 m = *(const float4*)mp;
        mp += E_;
        acc.x += a * m.x; acc.y += a * m.y;
        acc.z += a * m.z; acc.w += a * m.w;
    }
    *((float4*)(g_part + (size_t)(b * CCHUNKS + chunk) * E_) + tid) = acc;
}

__global__ void ctx_reduce_kernel(float* __restrict__ ctx_out) {
    int b = blockIdx.x, e = threadIdx.x;  // 512 threads
    float s = 0.f;
    #pragma unroll
    for (int c = 0; c < CCHUNKS; ++c)
        s += g_part[(size_t)(b * CCHUNKS + c) * E_ + e];
    ctx_out[b * E_ + e] = s;
}

// ---------------------------------------------------------------------------
extern "C" void kernel_launch(void* const* d_in, const int* in_sizes, int n_in,
                              void* d_out, int out_size) {
    const float* query  = (const float*)d_in[0];  // [64,1024]
    const float* memory = (const float*)d_in[1];  // [64,2000,512]
    const float* aw     = (const float*)d_in[2];  // [64,2000,2]
    const float* Wq     = (const float*)d_in[3];  // [128,1024]
    const float* Wm     = (const float*)d_in[4];  // [128,512]
    const float* Wloc   = (const float*)d_in[5];  // [128,2,31]
    const float* v      = (const float*)d_in[6];  // [128]

    float* ctx = (float*)d_out;                   // [64,512]
    float* aligns = ctx + B_ * E_;                // [64,2000]

    cudaFuncSetAttribute(scores_kernel,
                         cudaFuncAttributeMaxDynamicSharedMemorySize, SMEM_BYTES);

    pq_kernel<<<B_, 128>>>(query, Wq);
    scores_kernel<<<dim3(NTILES, B_), 256, SMEM_BYTES>>>(memory, aw, Wm, Wloc, v);
    softmax_kernel<<<B_, 256>>>(aligns);
    ctx_part_kernel<<<dim3(CCHUNKS, B_), 128>>>(memory, aligns);
    ctx_reduce_kernel<<<B_, 512>>>(ctx);
}

// round 3
// speedup vs baseline: 2.2465x; 2.2465x over previous
#include <cuda_runtime.h>
#include <cuda_fp16.h>
#include <math.h>
#include <stdint.h>

#define B_   64
#define T_   2000
#define E_   512
#define D_   1024
#define A_   128
#define PAD_ 15
#define NTILES  16
#define NCHUNKS 9          // chunk 0 = conv (im2col), 1..8 = memory K
#define CCH  25            // context chunks (2000 = 25*80)
#define CLEN 80

// ---- device scratch (allocation-free rule) ----
__device__ __align__(16) float  g_pq[B_ * A_];
__device__ __align__(16) float  g_scores[B_ * T_];
__device__ __align__(16) float  g_part[B_ * CCH * E_];
__device__ __align__(16) __half g_WmH[A_ * E_], g_WmL[A_ * E_];
__device__ __align__(16) __half g_WlocH[A_ * 64], g_WlocL[A_ * 64];

// ---- smem layout (bytes) ----
#define S_AW   0            // 2 x 160 floats = 1280
#define S_PQ   1280         // 128 floats
#define S_V    1792         // 128 floats
#define S_SC   2304         // 256 floats = 1024
#define S_BUF  3456
#define RS     144          // row stride bytes (72 halves) -> conflict-free ldmatrix
#define TSZ    (128 * RS)   // 18432 per tensor
#define OFF_AH 0
#define OFF_AL TSZ
#define OFF_BH (2 * TSZ)
#define OFF_BL (3 * TSZ)
#define BUFSZ  (4 * TSZ)    // 73728
#define SMEM_TC (S_BUF + 2 * BUFSZ)   // 150912

// ---------------- PTX helpers ----------------
__device__ __forceinline__ uint32_t smem_u32(const void* p) {
    uint32_t a;
    asm("{ .reg .u64 t; cvta.to.shared.u64 t, %1; cvt.u32.u64 %0, t; }"
        : "=r"(a) : "l"(p));
    return a;
}
__device__ __forceinline__ void cp16(uint32_t dst, const void* src) {
    asm volatile("cp.async.cg.shared.global [%0], [%1], 16;"
                 :: "r"(dst), "l"(src) : "memory");
}
__device__ __forceinline__ void cp_commit() {
    asm volatile("cp.async.commit_group;" ::: "memory");
}
__device__ __forceinline__ void cp_wait0() {
    asm volatile("cp.async.wait_group 0;" ::: "memory");
}
#define LDSM4(R, addr)                                                        \
    asm volatile("ldmatrix.sync.aligned.m8n8.x4.shared.b16 {%0,%1,%2,%3}, [%4];" \
                 : "=r"((R)[0]), "=r"((R)[1]), "=r"((R)[2]), "=r"((R)[3])     \
                 : "r"(addr))
#define MMA16816(acc, Af, b0, b1)                                             \
    asm volatile("mma.sync.aligned.m16n8k16.row.col.f32.f16.f16.f32 "         \
                 "{%0,%1,%2,%3},{%4,%5,%6,%7},{%8,%9},{%0,%1,%2,%3};"         \
                 : "+f"((acc)[0]), "+f"((acc)[1]), "+f"((acc)[2]), "+f"((acc)[3]) \
                 : "r"((Af)[0]), "r"((Af)[1]), "r"((Af)[2]), "r"((Af)[3]),    \
                   "r"(b0), "r"(b1))

__device__ __forceinline__ void split2(float x, float y,
                                       uint32_t& hi, uint32_t& lo) {
    __half hx = __float2half_rn(x), hy = __float2half_rn(y);
    __half lx = __float2half_rn(x - __half2float(hx));
    __half ly = __float2half_rn(y - __half2float(hy));
    __half2 H = __halves2half2(hx, hy), L = __halves2half2(lx, ly);
    hi = *(uint32_t*)&H;
    lo = *(uint32_t*)&L;
}

// ---------------------------------------------------------------------------
// prep: split Wm / Wloc into fp16 hi/lo
// ---------------------------------------------------------------------------
__global__ void prep_kernel(const float* __restrict__ Wm,
                            const float* __restrict__ Wloc) {
    int idx = blockIdx.x * 256 + threadIdx.x;    // grid 256 -> 65536
    float x = Wm[idx];
    __half h = __float2half_rn(x);
    __half l = __float2half_rn(x - __half2float(h));
    g_WmH[idx] = h;
    g_WmL[idx] = l;
    if (idx < A_ * 64) {
        int j = idx & 63;
        float w = (j < 62) ? Wloc[(idx >> 6) * 62 + j] : 0.f;
        __half wh = __float2half_rn(w);
        __half wl = __float2half_rn(w - __half2float(wh));
        g_WlocH[idx] = wh;
        g_WlocL[idx] = wl;
    }
}

// ---------------------------------------------------------------------------
// pq[b][a] = query[b] . Wq[a]
// ---------------------------------------------------------------------------
__global__ void pq_kernel(const float* __restrict__ query,
                          const float* __restrict__ Wq) {
    int b = blockIdx.x;
    int warp = threadIdx.x >> 5, lane = threadIdx.x & 31;
    const float* q = query + (size_t)b * D_;
    for (int a = warp; a < A_; a += 4) {
        const float* w = Wq + (size_t)a * D_;
        float s = 0.f;
        for (int k = lane; k < D_; k += 32) s += q[k] * w[k];
        #pragma unroll
        for (int off = 16; off; off >>= 1)
            s += __shfl_xor_sync(0xffffffffu, s, off);
        if (lane == 0) g_pq[b * A_ + a] = s;
    }
}

// ---------------------------------------------------------------------------
// scores via fp16-split HMMA (mma.sync m16n8k16), hi*hi + hi*lo + lo*hi
// ---------------------------------------------------------------------------
__global__ void __launch_bounds__(256)
scores_mma_kernel(const float* __restrict__ memory,
                  const float* __restrict__ aw,
                  const float* __restrict__ v) {
    extern __shared__ unsigned char smem[];
    const uint32_t sb = smem_u32(smem);
    const int tid = threadIdx.x;
    const int wid = tid >> 5, lid = tid & 31;
    const int b = blockIdx.y;
    const int t0 = blockIdx.x * 128;

    float* sAw = (float*)(smem + S_AW);     // [2][160]
    float* sPQ = (float*)(smem + S_PQ);
    float* sV  = (float*)(smem + S_V);
    float* sSc = (float*)(smem + S_SC);     // [2][128]

    const int warpT = wid >> 1, warpA = wid & 1;
    const int tBase = warpT * 32;            // 32 t rows per warp
    const int aBase = warpA * 64;            // 64 a cols per warp

    // ldmatrix per-lane offsets
    const int aRowOff = (lid & 7) + ((lid >> 3) & 1) * 8;
    const int aColB   = (lid >> 4) * 16;          // bytes
    const int bRowOff = (lid & 7) + (lid >> 4) * 8;
    const int bColB   = ((lid >> 3) & 1) * 16;    // bytes

    // A convert/store mapping: row r = tid/2, 32 cols at half*32
    const int cr = tid >> 1, ch = tid & 1;

    // aw window [t0-15, t0+143)
    for (int i = tid; i < 158; i += 256) {
        int tg = t0 - PAD_ + i;
        float c0 = 0.f, c1 = 0.f;
        if (tg >= 0 && tg < T_) {
            const float* p = aw + ((size_t)b * T_ + tg) * 2;
            c0 = p[0]; c1 = p[1];
        }
        sAw[i] = c0;
        sAw[160 + i] = c1;
    }
    if (tid < 128) { sPQ[tid] = g_pq[b * A_ + tid]; sV[tid] = v[tid]; }
    __syncthreads();

    // -------- prologue: chunk 0 (conv) into buf0 --------
    {
        unsigned char* buf = smem + S_BUF;
        // A: im2col of aw window, split hi/lo
        float xv[8];
        #pragma unroll
        for (int j2 = 0; j2 < 4; ++j2) {
            #pragma unroll
            for (int e = 0; e < 8; ++e) {
                int j = ch * 32 + j2 * 8 + e;
                float x = 0.f;
                if (j < 62) {
                    int c = (j >= 31);
                    x = sAw[c * 160 + cr + (j - c * 31)];
                }
                xv[e] = x;
            }
            uint4 H, L;
            split2(xv[0], xv[1], H.x, L.x);
            split2(xv[2], xv[3], H.y, L.y);
            split2(xv[4], xv[5], H.z, L.z);
            split2(xv[6], xv[7], H.w, L.w);
            int dst = cr * RS + ch * 64 + j2 * 16;
            *(uint4*)(buf + OFF_AH + dst) = H;
            *(uint4*)(buf + OFF_AL + dst) = L;
        }
        // B: Wloc hi/lo via cp.async (rows of 64 halves = 128B)
        #pragma unroll
        for (int it = 0; it < 4; ++it) {
            int idx = it * 256 + tid;
            int row = idx >> 3, q = idx & 7;
            cp16(sb + S_BUF + OFF_BH + row * RS + q * 16, g_WlocH + row * 64 + q * 8);
            cp16(sb + S_BUF + OFF_BL + row * RS + q * 16, g_WlocL + row * 64 + q * 8);
        }
        cp_commit();
        cp_wait0();
    }
    __syncthreads();

    float acc[2][8][4];
    #pragma unroll
    for (int m = 0; m < 2; ++m)
        #pragma unroll
        for (int n = 0; n < 8; ++n)
            #pragma unroll
            for (int e = 0; e < 4; ++e) acc[m][n][e] = 0.f;

    for (int c = 0; c < NCHUNKS; ++c) {
        const uint32_t curo = S_BUF + (uint32_t)(c & 1) * BUFSZ;
        const uint32_t nxto = S_BUF + (uint32_t)((c + 1) & 1) * BUFSZ;
        const bool have_next = (c + 1 < NCHUNKS);

        float4 a8[8];
        if (have_next) {
            const int kb = c * 64;   // chunk c+1 -> kbase = ((c+1)-1)*64
            // B(c+1) via cp.async
            const __half* WH = g_WmH + kb;
            const __half* WL = g_WmL + kb;
            #pragma unroll
            for (int it = 0; it < 4; ++it) {
                int idx = it * 256 + tid;
                int row = idx >> 3, q = idx & 7;
                cp16(nxto + sb + OFF_BH + row * RS + q * 16,
                     WH + (size_t)row * E_ + q * 8);
                cp16(nxto + sb + OFF_BL + row * RS + q * 16,
                     WL + (size_t)row * E_ + q * 8);
            }
            cp_commit();
            // A(c+1) to regs
            int gt = t0 + cr;
            if (gt < T_) {
                const float* src = memory + ((size_t)b * T_ + gt) * E_ + kb + ch * 32;
                #pragma unroll
                for (int j = 0; j < 8; ++j) a8[j] = *(const float4*)(src + j * 4);
            } else {
                #pragma unroll
                for (int j = 0; j < 8; ++j) a8[j] = make_float4(0.f, 0.f, 0.f, 0.f);
            }
        }

        // ---- MMA over current chunk ----
        {
            uint32_t aAddrH = sb + curo + OFF_AH + (uint32_t)(tBase + aRowOff) * RS + aColB;
            uint32_t bAddrH = sb + curo + OFF_BH + (uint32_t)(aBase + bRowOff) * RS + bColB;
            #pragma unroll
            for (int ks = 0; ks < 4; ++ks) {
                uint32_t ah[2][4], al[2][4];
                #pragma unroll
                for (int m = 0; m < 2; ++m) {
                    uint32_t ad = aAddrH + (uint32_t)(m * 16) * RS + ks * 32;
                    LDSM4(ah[m], ad);
                    LDSM4(al[m], ad + TSZ);
                }
                uint32_t bh[4][4], bl[4][4];
                #pragma unroll
                for (int g = 0; g < 4; ++g) {
                    uint32_t bd = bAddrH + (uint32_t)(g * 16) * RS + ks * 32;
                    LDSM4(bh[g], bd);
                    LDSM4(bl[g], bd + TSZ);
                }
                #pragma unroll
                for (int m = 0; m < 2; ++m) {
                    #pragma unroll
                    for (int g = 0; g < 4; ++g) {
                        MMA16816(acc[m][2 * g],     ah[m], bh[g][0], bh[g][1]);
                        MMA16816(acc[m][2 * g + 1], ah[m], bh[g][2], bh[g][3]);
                        MMA16816(acc[m][2 * g],     ah[m], bl[g][0], bl[g][1]);
                        MMA16816(acc[m][2 * g + 1], ah[m], bl[g][2], bl[g][3]);
                        MMA16816(acc[m][2 * g],     al[m], bh[g][0], bh[g][1]);
                        MMA16816(acc[m][2 * g + 1], al[m], bh[g][2], bh[g][3]);
                    }
                }
            }
        }

        if (have_next) {
            // convert + store A(c+1)
            unsigned char* nb = smem + nxto - 0;   // generic ptr
            #pragma unroll
            for (int j2 = 0; j2 < 4; ++j2) {
                float4 x = a8[2 * j2], y = a8[2 * j2 + 1];
                uint4 H, L;
                split2(x.x, x.y, H.x, L.x);
                split2(x.z, x.w, H.y, L.y);
                split2(y.x, y.y, H.z, L.z);
                split2(y.z, y.w, H.w, L.w);
                int dst = cr * RS + ch * 64 + j2 * 16;
                *(uint4*)(nb + OFF_AH + dst) = H;
                *(uint4*)(nb + OFF_AL + dst) = L;
            }
            cp_wait0();
        }
        __syncthreads();
    }

    // ---- epilogue: score[t] = sum_a v[a]*tanh(acc + pq[a]) ----
    {
        float s[4] = {0.f, 0.f, 0.f, 0.f};   // {m0r0, m0r1, m1r0, m1r1}
        #pragma unroll
        for (int m = 0; m < 2; ++m) {
            #pragma unroll
            for (int n = 0; n < 8; ++n) {
                int a0 = aBase + n * 8 + (lid & 3) * 2;
                float v0 = sV[a0], v1 = sV[a0 + 1];
                float q0 = sPQ[a0], q1 = sPQ[a0 + 1];
                s[2 * m]     += v0 * tanhf(acc[m][n][0] + q0)
                              + v1 * tanhf(acc[m][n][1] + q1);
                s[2 * m + 1] += v0 * tanhf(acc[m][n][2] + q0)
                              + v1 * tanhf(acc[m][n][3] + q1);
            }
        }
        #pragma unroll
        for (int off = 1; off < 4; off <<= 1) {
            #pragma unroll
            for (int i = 0; i < 4; ++i)
                s[i] += __shfl_xor_sync(0xffffffffu, s[i], off);
        }
        if ((lid & 3) == 0) {
            int r = tBase + (lid >> 2);
            sSc[warpA * 128 + r]      = s[0];
            sSc[warpA * 128 + r + 8]  = s[1];
            sSc[warpA * 128 + r + 16] = s[2];
            sSc[warpA * 128 + r + 24] = s[3];
        }
    }
    __syncthreads();
    if (tid < 128) {
        int gt = t0 + tid;
        if (gt < T_) g_scores[b * T_ + gt] = sSc[tid] + sSc[128 + tid];
    }
}

// ---------------------------------------------------------------------------
// softmax over T per batch row
// ---------------------------------------------------------------------------
__global__ void softmax_kernel(float* __restrict__ align_out) {
    __shared__ float buf[T_];
    __shared__ float red[256];
    int b = blockIdx.x, tid = threadIdx.x;
    float mx = -1e30f;
    for (int t = tid; t < T_; t += 256) {
        float s = g_scores[b * T_ + t];
        buf[t] = s;
        mx = fmaxf(mx, s);
    }
    red[tid] = mx;
    __syncthreads();
    for (int off = 128; off; off >>= 1) {
        if (tid < off) red[tid] = fmaxf(red[tid], red[tid + off]);
        __syncthreads();
    }
    mx = red[0];
    __syncthreads();
    float sum = 0.f;
    for (int t = tid; t < T_; t += 256) {
        float e = __expf(buf[t] - mx);
        buf[t] = e;
        sum += e;
    }
    red[tid] = sum;
    __syncthreads();
    for (int off = 128; off; off >>= 1) {
        if (tid < off) red[tid] += red[tid + off];
        __syncthreads();
    }
    float inv = 1.f / red[0];
    for (int t = tid; t < T_; t += 256) align_out[b * T_ + t] = buf[t] * inv;
}

// ---------------------------------------------------------------------------
// context partials: 25 chunks of 80 (deterministic, no atomics)
// ---------------------------------------------------------------------------
__global__ void ctx_part_kernel(const float* __restrict__ memory,
                                const float* __restrict__ aligns) {
    int chunk = blockIdx.x, b = blockIdx.y, tid = threadIdx.x;  // 128 threads
    __shared__ float sa[CLEN];
    const float* al = aligns + (size_t)b * T_ + chunk * CLEN;
    if (tid < CLEN) sa[tid] = al[tid];
    __syncthreads();
    const float* mp = memory + ((size_t)b * T_ + (size_t)chunk * CLEN) * E_ + tid * 4;
    float4 acc = make_float4(0.f, 0.f, 0.f, 0.f);
    #pragma unroll 8
    for (int tt = 0; tt < CLEN; ++tt) {
        float a = sa[tt];
        float4 m = *(const float4*)mp;
        mp += E_;
        acc.x += a * m.x; acc.y += a * m.y;
        acc.z += a * m.z; acc.w += a * m.w;
    }
    *((float4*)(g_part + ((size_t)b * CCH + chunk) * E_) + tid) = acc;
}

__global__ void ctx_reduce_kernel(float* __restrict__ ctx_out) {
    int b = blockIdx.x, e = threadIdx.x;  // 512 threads
    float s = 0.f;
    #pragma unroll
    for (int c = 0; c < CCH; ++c)
        s += g_part[((size_t)b * CCH + c) * E_ + e];
    ctx_out[b * E_ + e] = s;
}

// ---------------------------------------------------------------------------
extern "C" void kernel_launch(void* const* d_in, const int* in_sizes, int n_in,
                              void* d_out, int out_size) {
    const float* query  = (const float*)d_in[0];  // [64,1024]
    const float* memory = (const float*)d_in[1];  // [64,2000,512]
    const float* aw     = (const float*)d_in[2];  // [64,2000,2]
    const float* Wq     = (const float*)d_in[3];  // [128,1024]
    const float* Wm     = (const float*)d_in[4];  // [128,512]
    const float* Wloc   = (const float*)d_in[5];  // [128,2,31]
    const float* v      = (const float*)d_in[6];  // [128]

    float* ctx = (float*)d_out;                   // [64,512]
    float* aligns = ctx + B_ * E_;                // [64,2000]

    cudaFuncSetAttribute(scores_mma_kernel,
                         cudaFuncAttributeMaxDynamicSharedMemorySize, SMEM_TC);

    prep_kernel<<<256, 256>>>(Wm, Wloc);
    pq_kernel<<<B_, 128>>>(query, Wq);
    scores_mma_kernel<<<dim3(NTILES, B_), 256, SMEM_TC>>>(memory, aw, v);
    softmax_kernel<<<B_, 256>>>(aligns);
    ctx_part_kernel<<<dim3(CCH, B_), 128>>>(memory, aligns);
    ctx_reduce_kernel<<<B_, 512>>>(ctx);
}

// round 4
// speedup vs baseline: 2.3999x; 1.0683x over previous
#include <cuda_runtime.h>
#include <cuda_fp16.h>
#include <math.h>
#include <stdint.h>

#define B_   64
#define T_   2000
#define E_   512
#define D_   1024
#define A_   128
#define PAD_ 15
#define TTILE  64
#define NTILES 32          // ceil(2000/64)
#define NCHUNKS 9          // chunk 0 = conv (im2col), 1..8 = memory K
#define CCH  25            // context chunks (2000 = 25*80)
#define CLEN 80

// ---- device scratch (allocation-free rule) ----
__device__ __align__(16) float  g_pq[B_ * A_];
__device__ __align__(16) float  g_scores[B_ * T_];
__device__ __align__(16) float  g_part[B_ * CCH * E_];
__device__ __align__(16) __half g_WmH[A_ * E_], g_WmL[A_ * E_];
__device__ __align__(16) __half g_WlocH[A_ * 64], g_WlocL[A_ * 64];

// ---- smem layout (bytes) ----
#define S_AW   0            // 2 x 96 floats = 768
#define S_PQ   768          // 128 floats
#define S_V    1280         // 128 floats
#define S_SC   1792         // 2 x 64 floats = 512
#define S_BUF  2304
#define OFF_A  S_BUF        // 2 bufs x 16384 (AH 8192 + AL 8192), 64 rows x 128B
#define OFF_B  (S_BUF + 32768)  // 2 bufs x 32768 (BH 16384 + BL 16384), 128 rows x 128B
#define SMEM_TOTAL (S_BUF + 32768 + 65536)   // 100608

// ---------------- PTX helpers ----------------
__device__ __forceinline__ uint32_t smem_u32(const void* p) {
    uint32_t a;
    asm("{ .reg .u64 t; cvta.to.shared.u64 t, %1; cvt.u32.u64 %0, t; }"
        : "=r"(a) : "l"(p));
    return a;
}
__device__ __forceinline__ void cp16(uint32_t dst, const void* src) {
    asm volatile("cp.async.cg.shared.global [%0], [%1], 16;"
                 :: "r"(dst), "l"(src) : "memory");
}
__device__ __forceinline__ void cp_commit() {
    asm volatile("cp.async.commit_group;" ::: "memory");
}
__device__ __forceinline__ void cp_wait0() {
    asm volatile("cp.async.wait_group 0;" ::: "memory");
}
#define LDSM4(R, addr)                                                        \
    asm volatile("ldmatrix.sync.aligned.m8n8.x4.shared.b16 {%0,%1,%2,%3}, [%4];" \
                 : "=r"((R)[0]), "=r"((R)[1]), "=r"((R)[2]), "=r"((R)[3])     \
                 : "r"(addr))
#define MMA16816(acc, Af, b0, b1)                                             \
    asm volatile("mma.sync.aligned.m16n8k16.row.col.f32.f16.f16.f32 "         \
                 "{%0,%1,%2,%3},{%4,%5,%6,%7},{%8,%9},{%0,%1,%2,%3};"         \
                 : "+f"((acc)[0]), "+f"((acc)[1]), "+f"((acc)[2]), "+f"((acc)[3]) \
                 : "r"((Af)[0]), "r"((Af)[1]), "r"((Af)[2]), "r"((Af)[3]),    \
                   "r"(b0), "r"(b1))

__device__ __forceinline__ void split2(float x, float y,
                                       uint32_t& hi, uint32_t& lo) {
    __half hx = __float2half_rn(x), hy = __float2half_rn(y);
    __half lx = __float2half_rn(x - __half2float(hx));
    __half ly = __float2half_rn(y - __half2float(hy));
    __half2 H = __halves2half2(hx, hy), L = __halves2half2(lx, ly);
    hi = *(uint32_t*)&H;
    lo = *(uint32_t*)&L;
}
// XOR swizzle: 16B chunk c (0..7) within a 128B row
__device__ __forceinline__ uint32_t swzo(uint32_t row, uint32_t c) {
    return (row << 7) + (((c ^ row) & 7u) << 4) + ((c & ~7u) << 4);
}

// ---------------------------------------------------------------------------
// prep: split Wm / Wloc into fp16 hi/lo
// ---------------------------------------------------------------------------
__global__ void prep_kernel(const float* __restrict__ Wm,
                            const float* __restrict__ Wloc) {
    int idx = blockIdx.x * 256 + threadIdx.x;    // grid 256 -> 65536
    float x = Wm[idx];
    __half h = __float2half_rn(x);
    __half l = __float2half_rn(x - __half2float(h));
    g_WmH[idx] = h;
    g_WmL[idx] = l;
    if (idx < A_ * 64) {
        int j = idx & 63;
        float w = (j < 62) ? Wloc[(idx >> 6) * 62 + j] : 0.f;
        __half wh = __float2half_rn(w);
        __half wl = __float2half_rn(w - __half2float(wh));
        g_WlocH[idx] = wh;
        g_WlocL[idx] = wl;
    }
}

// ---------------------------------------------------------------------------
// pq[b][a] = query[b] . Wq[a]
// ---------------------------------------------------------------------------
__global__ void pq_kernel(const float* __restrict__ query,
                          const float* __restrict__ Wq) {
    int b = blockIdx.x;
    int warp = threadIdx.x >> 5, lane = threadIdx.x & 31;
    const float* q = query + (size_t)b * D_;
    for (int a = warp; a < A_; a += 4) {
        const float* w = Wq + (size_t)a * D_;
        float s = 0.f;
        for (int k = lane; k < D_; k += 32) s += q[k] * w[k];
        #pragma unroll
        for (int off = 16; off; off >>= 1)
            s += __shfl_xor_sync(0xffffffffu, s, off);
        if (lane == 0) g_pq[b * A_ + a] = s;
    }
}

// ---------------------------------------------------------------------------
// scores via fp16-split HMMA. 64t x 128a tile, 128 threads, 2 CTAs/SM.
// ---------------------------------------------------------------------------
__global__ void __launch_bounds__(128, 2)
scores_mma_kernel(const float* __restrict__ memory,
                  const float* __restrict__ aw,
                  const float* __restrict__ v) {
    extern __shared__ unsigned char smem[];
    const uint32_t sb = smem_u32(smem);
    const int tid = threadIdx.x;
    const int wid = tid >> 5, lid = tid & 31;
    const int b = blockIdx.y;
    const int t0 = blockIdx.x * TTILE;

    float* sAw = (float*)(smem + S_AW);     // [2][96]
    float* sPQ = (float*)(smem + S_PQ);
    float* sV  = (float*)(smem + S_V);
    float* sSc = (float*)(smem + S_SC);     // [2][64]

    const int warpT = wid >> 1, warpA = wid & 1;
    const int tBase = warpT * 32;            // 32 t rows per warp
    const int aBase = warpA * 64;            // 64 a cols per warp

    // ldmatrix per-lane row offsets (tile-local)
    const int aRowOff = (lid & 7) + ((lid >> 3) & 1) * 8;
    const uint32_t aCk = (uint32_t)(lid >> 4);          // A chunk lane bit
    const int bRowOff = (lid & 7) + (lid >> 4) * 8;
    const uint32_t bCk = (uint32_t)((lid >> 3) & 1);    // B chunk lane bit
    const uint32_t rx = (uint32_t)(lid & 7);            // swizzle xor (row & 7)

    // A convert/store mapping: row cr = tid/2, half ch covers 32 halves
    const int cr = tid >> 1, ch = tid & 1;
    const uint32_t crx = (uint32_t)(cr & 7);

    // aw window [t0-15, t0+79)
    for (int i = tid; i < TTILE + 2 * PAD_; i += 128) {
        int tg = t0 - PAD_ + i;
        float c0 = 0.f, c1 = 0.f;
        if (tg >= 0 && tg < T_) {
            const float* p = aw + ((size_t)b * T_ + tg) * 2;
            c0 = p[0]; c1 = p[1];
        }
        sAw[i] = c0;
        sAw[96 + i] = c1;
    }
    sPQ[tid] = g_pq[b * A_ + tid];
    sV[tid] = v[tid];
    __syncthreads();

    // -------- prologue: chunk 0 (conv) --------
    {
        unsigned char* abuf = smem + OFF_A;   // buffer 0
        float xv[8];
        #pragma unroll
        for (int j2 = 0; j2 < 4; ++j2) {
            #pragma unroll
            for (int e = 0; e < 8; ++e) {
                int j = ch * 32 + j2 * 8 + e;
                float x = 0.f;
                if (j < 62) {
                    int c = (j >= 31);
                    x = sAw[c * 96 + cr + (j - c * 31)];
                }
                xv[e] = x;
            }
            uint4 H, L;
            split2(xv[0], xv[1], H.x, L.x);
            split2(xv[2], xv[3], H.y, L.y);
            split2(xv[4], xv[5], H.z, L.z);
            split2(xv[6], xv[7], H.w, L.w);
            uint32_t c = (uint32_t)(ch * 4 + j2);
            uint32_t dst = (uint32_t)(cr << 7) + (((c ^ crx) & 7u) << 4);
            *(uint4*)(abuf + dst) = H;
            *(uint4*)(abuf + 8192 + dst) = L;
        }
        // B: Wloc hi/lo via cp.async
        #pragma unroll
        for (int it = 0; it < 8; ++it) {
            int idx = it * 128 + tid;          // 1024 (row,chunk) pairs
            uint32_t row = (uint32_t)(idx >> 3), q = (uint32_t)(idx & 7);
            uint32_t dst = sb + OFF_B + (row << 7) + (((q ^ row) & 7u) << 4);
            cp16(dst, g_WlocH + row * 64 + q * 8);
            cp16(dst + 16384, g_WlocL + row * 64 + q * 8);
        }
        cp_commit();
        cp_wait0();
    }
    __syncthreads();

    float acc[2][8][4];
    #pragma unroll
    for (int m = 0; m < 2; ++m)
        #pragma unroll
        for (int n = 0; n < 8; ++n)
            #pragma unroll
            for (int e = 0; e < 4; ++e) acc[m][n][e] = 0.f;

    // precomputed row byte offsets
    uint32_t aRowB[2], bRowB[4];
    #pragma unroll
    for (int m = 0; m < 2; ++m) aRowB[m] = (uint32_t)(tBase + m * 16 + aRowOff) << 7;
    #pragma unroll
    for (int g = 0; g < 4; ++g) bRowB[g] = (uint32_t)(aBase + g * 16 + bRowOff) << 7;

    for (int c = 0; c < NCHUNKS; ++c) {
        const uint32_t curA = sb + OFF_A + (uint32_t)(c & 1) * 16384;
        const uint32_t curB = sb + OFF_B + (uint32_t)(c & 1) * 32768;
        const bool have_next = (c + 1 < NCHUNKS);

        float4 a8[8];
        if (have_next) {
            const int kb = c * 64;   // chunk c+1 -> kbase = c*64
            const uint32_t nxtB = sb + OFF_B + (uint32_t)((c + 1) & 1) * 32768;
            const __half* WH = g_WmH + kb;
            const __half* WL = g_WmL + kb;
            #pragma unroll
            for (int it = 0; it < 8; ++it) {
                int idx = it * 128 + tid;
                uint32_t row = (uint32_t)(idx >> 3), q = (uint32_t)(idx & 7);
                uint32_t dst = nxtB + (row << 7) + (((q ^ row) & 7u) << 4);
                cp16(dst, WH + (size_t)row * E_ + q * 8);
                cp16(dst + 16384, WL + (size_t)row * E_ + q * 8);
            }
            cp_commit();
            int gt = t0 + cr;
            if (gt < T_) {
                const float* src = memory + ((size_t)b * T_ + gt) * E_ + kb + ch * 32;
                #pragma unroll
                for (int j = 0; j < 8; ++j) a8[j] = *(const float4*)(src + j * 4);
            } else {
                #pragma unroll
                for (int j = 0; j < 8; ++j) a8[j] = make_float4(0.f, 0.f, 0.f, 0.f);
            }
        }

        // ---- MMA over current chunk ----
        #pragma unroll
        for (int ks = 0; ks < 4; ++ks) {
            uint32_t ah[2][4], al[2][4];
            #pragma unroll
            for (int m = 0; m < 2; ++m) {
                uint32_t ad = curA + aRowB[m] +
                              ((((uint32_t)(2 * ks) + aCk) ^ rx) << 4);
                LDSM4(ah[m], ad);
                LDSM4(al[m], ad + 8192);
            }
            uint32_t bh[4][4], bl[4][4];
            #pragma unroll
            for (int g = 0; g < 4; ++g) {
                uint32_t bd = curB + bRowB[g] +
                              ((((uint32_t)(2 * ks) + bCk) ^ rx) << 4);
                LDSM4(bh[g], bd);
                LDSM4(bl[g], bd + 16384);
            }
            #pragma unroll
            for (int m = 0; m < 2; ++m) {
                #pragma unroll
                for (int g = 0; g < 4; ++g) {
                    MMA16816(acc[m][2 * g],     ah[m], bh[g][0], bh[g][1]);
                    MMA16816(acc[m][2 * g + 1], ah[m], bh[g][2], bh[g][3]);
                    MMA16816(acc[m][2 * g],     ah[m], bl[g][0], bl[g][1]);
                    MMA16816(acc[m][2 * g + 1], ah[m], bl[g][2], bl[g][3]);
                    MMA16816(acc[m][2 * g],     al[m], bh[g][0], bh[g][1]);
                    MMA16816(acc[m][2 * g + 1], al[m], bh[g][2], bh[g][3]);
                }
            }
        }

        if (have_next) {
            unsigned char* nb = smem + OFF_A + ((c + 1) & 1) * 16384;
            #pragma unroll
            for (int j2 = 0; j2 < 4; ++j2) {
                float4 x = a8[2 * j2], y = a8[2 * j2 + 1];
                uint4 H, L;
                split2(x.x, x.y, H.x, L.x);
                split2(x.z, x.w, H.y, L.y);
                split2(y.x, y.y, H.z, L.z);
                split2(y.z, y.w, H.w, L.w);
                uint32_t cc = (uint32_t)(ch * 4 + j2);
                uint32_t dst = (uint32_t)(cr << 7) + (((cc ^ crx) & 7u) << 4);
                *(uint4*)(nb + dst) = H;
                *(uint4*)(nb + 8192 + dst) = L;
            }
            cp_wait0();
        }
        __syncthreads();
    }

    // ---- epilogue: score[t] = sum_a v[a]*tanh(acc + pq[a]) ----
    {
        float s[4] = {0.f, 0.f, 0.f, 0.f};
        #pragma unroll
        for (int m = 0; m < 2; ++m) {
            #pragma unroll
            for (int n = 0; n < 8; ++n) {
                int a0 = aBase + n * 8 + (lid & 3) * 2;
                float v0 = sV[a0], v1 = sV[a0 + 1];
                float q0 = sPQ[a0], q1 = sPQ[a0 + 1];
                s[2 * m]     += v0 * tanhf(acc[m][n][0] + q0)
                              + v1 * tanhf(acc[m][n][1] + q1);
                s[2 * m + 1] += v0 * tanhf(acc[m][n][2] + q0)
                              + v1 * tanhf(acc[m][n][3] + q1);
            }
        }
        #pragma unroll
        for (int off = 1; off < 4; off <<= 1) {
            #pragma unroll
            for (int i = 0; i < 4; ++i)
                s[i] += __shfl_xor_sync(0xffffffffu, s[i], off);
        }
        if ((lid & 3) == 0) {
            int r = tBase + (lid >> 2);
            sSc[warpA * 64 + r]      = s[0];
            sSc[warpA * 64 + r + 8]  = s[1];
            sSc[warpA * 64 + r + 16] = s[2];
            sSc[warpA * 64 + r + 24] = s[3];
        }
    }
    __syncthreads();
    if (tid < TTILE) {
        int gt = t0 + tid;
        if (gt < T_) g_scores[b * T_ + gt] = sSc[tid] + sSc[64 + tid];
    }
}

// ---------------------------------------------------------------------------
// softmax over T per batch row (512 threads, shuffle reductions)
// ---------------------------------------------------------------------------
__global__ void softmax_kernel(float* __restrict__ align_out) {
    __shared__ float buf[T_];
    __shared__ float red[16];
    int b = blockIdx.x, tid = threadIdx.x;
    int wid = tid >> 5, lane = tid & 31;
    float mx = -1e30f;
    for (int t = tid; t < T_; t += 512) {
        float s = g_scores[b * T_ + t];
        buf[t] = s;
        mx = fmaxf(mx, s);
    }
    #pragma unroll
    for (int off = 16; off; off >>= 1)
        mx = fmaxf(mx, __shfl_xor_sync(0xffffffffu, mx, off));
    if (lane == 0) red[wid] = mx;
    __syncthreads();
    if (wid == 0) {
        float m2 = (lane < 16) ? red[lane] : -1e30f;
        #pragma unroll
        for (int off = 8; off; off >>= 1)
            m2 = fmaxf(m2, __shfl_xor_sync(0xffffffffu, m2, off));
        if (lane == 0) red[0] = m2;
    }
    __syncthreads();
    mx = red[0];
    __syncthreads();
    float sum = 0.f;
    for (int t = tid; t < T_; t += 512) {
        float e = __expf(buf[t] - mx);
        buf[t] = e;
        sum += e;
    }
    #pragma unroll
    for (int off = 16; off; off >>= 1)
        sum += __shfl_xor_sync(0xffffffffu, sum, off);
    if (lane == 0) red[wid] = sum;
    __syncthreads();
    if (wid == 0) {
        float s2 = (lane < 16) ? red[lane] : 0.f;
        #pragma unroll
        for (int off = 8; off; off >>= 1)
            s2 += __shfl_xor_sync(0xffffffffu, s2, off);
        if (lane == 0) red[0] = s2;
    }
    __syncthreads();
    float inv = 1.f / red[0];
    for (int t = tid; t < T_; t += 512) align_out[b * T_ + t] = buf[t] * inv;
}

// ---------------------------------------------------------------------------
// context partials: 25 chunks of 80 (deterministic, no atomics)
// ---------------------------------------------------------------------------
__global__ void ctx_part_kernel(const float* __restrict__ memory,
                                const float* __restrict__ aligns) {
    int chunk = blockIdx.x, b = blockIdx.y, tid = threadIdx.x;  // 128 threads
    __shared__ float sa[CLEN];
    const float* al = aligns + (size_t)b * T_ + chunk * CLEN;
    if (tid < CLEN) sa[tid] = al[tid];
    __syncthreads();
    const float* mp = memory + ((size_t)b * T_ + (size_t)chunk * CLEN) * E_ + tid * 4;
    float4 acc0 = make_float4(0.f, 0.f, 0.f, 0.f);
    float4 acc1 = make_float4(0.f, 0.f, 0.f, 0.f);
    #pragma unroll 4
    for (int tt = 0; tt < CLEN; tt += 2) {
        float a0 = sa[tt], a1 = sa[tt + 1];
        float4 m0 = *(const float4*)mp;
        float4 m1 = *(const float4*)(mp + E_);
        mp += 2 * E_;
        acc0.x += a0 * m0.x; acc0.y += a0 * m0.y;
        acc0.z += a0 * m0.z; acc0.w += a0 * m0.w;
        acc1.x += a1 * m1.x; acc1.y += a1 * m1.y;
        acc1.z += a1 * m1.z; acc1.w += a1 * m1.w;
    }
    acc0.x += acc1.x; acc0.y += acc1.y; acc0.z += acc1.z; acc0.w += acc1.w;
    *((float4*)(g_part + ((size_t)b * CCH + chunk) * E_) + tid) = acc0;
}

__global__ void ctx_reduce_kernel(float* __restrict__ ctx_out) {
    int b = blockIdx.x, e = threadIdx.x;  // 512 threads
    float s = 0.f;
    #pragma unroll
    for (int c = 0; c < CCH; ++c)
        s += g_part[((size_t)b * CCH + c) * E_ + e];
    ctx_out[b * E_ + e] = s;
}

// ---------------------------------------------------------------------------
extern "C" void kernel_launch(void* const* d_in, const int* in_sizes, int n_in,
                              void* d_out, int out_size) {
    const float* query  = (const float*)d_in[0];  // [64,1024]
    const float* memory = (const float*)d_in[1];  // [64,2000,512]
    const float* aw     = (const float*)d_in[2];  // [64,2000,2]
    const float* Wq     = (const float*)d_in[3];  // [128,1024]
    const float* Wm     = (const float*)d_in[4];  // [128,512]
    const float* Wloc   = (const float*)d_in[5];  // [128,2,31]
    const float* v      = (const float*)d_in[6];  // [128]

    float* ctx = (float*)d_out;                   // [64,512]
    float* aligns = ctx + B_ * E_;                // [64,2000]

    cudaFuncSetAttribute(scores_mma_kernel,
                         cudaFuncAttributeMaxDynamicSharedMemorySize, SMEM_TOTAL);

    prep_kernel<<<256, 256>>>(Wm, Wloc);
    pq_kernel<<<B_, 128>>>(query, Wq);
    scores_mma_kernel<<<dim3(NTILES, B_), 128, SMEM_TOTAL>>>(memory, aw, v);
    softmax_kernel<<<B_, 512>>>(aligns);
    ctx_part_kernel<<<dim3(CCH, B_), 128>>>(memory, aligns);
    ctx_reduce_kernel<<<B_, 512>>>(ctx);
}

// round 5
// speedup vs baseline: 2.4012x; 1.0005x over previous
#include <cuda_runtime.h>
#include <cuda_fp16.h>
#include <math.h>
#include <stdint.h>

#define B_   64
#define T_   2000
#define E_   512
#define D_   1024
#define A_   128
#define PAD_ 15
#define TTILE  64
#define NTILES 32          // ceil(2000/64)
#define NCHUNKS 9          // chunk 0 = conv (im2col), 1..8 = memory K
#define CCH  25            // context chunks (2000 = 25*80)
#define CLEN 80

// ---- device scratch (allocation-free rule) ----
__device__ __align__(16) float  g_pq[B_ * A_];
__device__ __align__(16) float  g_scores[B_ * T_];
__device__ __align__(16) float  g_part[B_ * CCH * E_];
__device__ __align__(16) __half g_WmH[A_ * E_], g_WmL[A_ * E_];
__device__ __align__(16) __half g_WlocH[A_ * 64], g_WlocL[A_ * 64];

// ---- smem layout (bytes) ----
#define S_AW   0            // 2 x 96 floats = 768
#define S_PQ   768          // 128 floats
#define S_V    1280         // 128 floats
#define S_SC   1792         // 2 x 64 floats = 512
#define S_BUF  2304
#define OFF_A  S_BUF        // 2 bufs x 16384 (AH 8192 + AL 8192), 64 rows x 128B
#define OFF_B  (S_BUF + 32768)  // 2 bufs x 32768 (BH 16384 + BL 16384), 128 rows x 128B
#define SMEM_TOTAL (S_BUF + 32768 + 65536)   // 100608

// ---------------- PTX helpers ----------------
__device__ __forceinline__ uint32_t smem_u32(const void* p) {
    uint32_t a;
    asm("{ .reg .u64 t; cvta.to.shared.u64 t, %1; cvt.u32.u64 %0, t; }"
        : "=r"(a) : "l"(p));
    return a;
}
__device__ __forceinline__ void cp16(uint32_t dst, const void* src) {
    asm volatile("cp.async.cg.shared.global [%0], [%1], 16;"
                 :: "r"(dst), "l"(src) : "memory");
}
__device__ __forceinline__ void cp_commit() {
    asm volatile("cp.async.commit_group;" ::: "memory");
}
__device__ __forceinline__ void cp_wait0() {
    asm volatile("cp.async.wait_group 0;" ::: "memory");
}
#define LDSM4(R, addr)                                                        \
    asm volatile("ldmatrix.sync.aligned.m8n8.x4.shared.b16 {%0,%1,%2,%3}, [%4];" \
                 : "=r"((R)[0]), "=r"((R)[1]), "=r"((R)[2]), "=r"((R)[3])     \
                 : "r"(addr))
#define MMA16816(acc, Af, b0, b1)                                             \
    asm volatile("mma.sync.aligned.m16n8k16.row.col.f32.f16.f16.f32 "         \
                 "{%0,%1,%2,%3},{%4,%5,%6,%7},{%8,%9},{%0,%1,%2,%3};"         \
                 : "+f"((acc)[0]), "+f"((acc)[1]), "+f"((acc)[2]), "+f"((acc)[3]) \
                 : "r"((Af)[0]), "r"((Af)[1]), "r"((Af)[2]), "r"((Af)[3]),    \
                   "r"(b0), "r"(b1))

__device__ __forceinline__ void split2(float x, float y,
                                       uint32_t& hi, uint32_t& lo) {
    __half hx = __float2half_rn(x), hy = __float2half_rn(y);
    __half lx = __float2half_rn(x - __half2float(hx));
    __half ly = __float2half_rn(y - __half2float(hy));
    __half2 H = __halves2half2(hx, hy), L = __halves2half2(lx, ly);
    hi = *(uint32_t*)&H;
    lo = *(uint32_t*)&L;
}
// XOR swizzle: 16B chunk c (0..7) within a 128B row
__device__ __forceinline__ uint32_t swzo(uint32_t row, uint32_t c) {
    return (row << 7) + (((c ^ row) & 7u) << 4) + ((c & ~7u) << 4);
}

// ---------------------------------------------------------------------------
// prep: split Wm / Wloc into fp16 hi/lo
// ---------------------------------------------------------------------------
__global__ void prep_kernel(const float* __restrict__ Wm,
                            const float* __restrict__ Wloc) {
    int idx = blockIdx.x * 256 + threadIdx.x;    // grid 256 -> 65536
    float x = Wm[idx];
    __half h = __float2half_rn(x);
    __half l = __float2half_rn(x - __half2float(h));
    g_WmH[idx] = h;
    g_WmL[idx] = l;
    if (idx < A_ * 64) {
        int j = idx & 63;
        float w = (j < 62) ? Wloc[(idx >> 6) * 62 + j] : 0.f;
        __half wh = __float2half_rn(w);
        __half wl = __float2half_rn(w - __half2float(wh));
        g_WlocH[idx] = wh;
        g_WlocL[idx] = wl;
    }
}

// ---------------------------------------------------------------------------
// pq[b][a] = query[b] . Wq[a]
// ---------------------------------------------------------------------------
__global__ void pq_kernel(const float* __restrict__ query,
                          const float* __restrict__ Wq) {
    int b = blockIdx.x;
    int warp = threadIdx.x >> 5, lane = threadIdx.x & 31;
    const float* q = query + (size_t)b * D_;
    for (int a = warp; a < A_; a += 4) {
        const float* w = Wq + (size_t)a * D_;
        float s = 0.f;
        for (int k = lane; k < D_; k += 32) s += q[k] * w[k];
        #pragma unroll
        for (int off = 16; off; off >>= 1)
            s += __shfl_xor_sync(0xffffffffu, s, off);
        if (lane == 0) g_pq[b * A_ + a] = s;
    }
}

// ---------------------------------------------------------------------------
// scores via fp16-split HMMA. 64t x 128a tile, 128 threads, 2 CTAs/SM.
// ---------------------------------------------------------------------------
__global__ void __launch_bounds__(128, 2)
scores_mma_kernel(const float* __restrict__ memory,
                  const float* __restrict__ aw,
                  const float* __restrict__ v) {
    extern __shared__ unsigned char smem[];
    const uint32_t sb = smem_u32(smem);
    const int tid = threadIdx.x;
    const int wid = tid >> 5, lid = tid & 31;
    const int b = blockIdx.y;
    const int t0 = blockIdx.x * TTILE;

    float* sAw = (float*)(smem + S_AW);     // [2][96]
    float* sPQ = (float*)(smem + S_PQ);
    float* sV  = (float*)(smem + S_V);
    float* sSc = (float*)(smem + S_SC);     // [2][64]

    const int warpT = wid >> 1, warpA = wid & 1;
    const int tBase = warpT * 32;            // 32 t rows per warp
    const int aBase = warpA * 64;            // 64 a cols per warp

    // ldmatrix per-lane row offsets (tile-local)
    const int aRowOff = (lid & 7) + ((lid >> 3) & 1) * 8;
    const uint32_t aCk = (uint32_t)(lid >> 4);          // A chunk lane bit
    const int bRowOff = (lid & 7) + (lid >> 4) * 8;
    const uint32_t bCk = (uint32_t)((lid >> 3) & 1);    // B chunk lane bit
    const uint32_t rx = (uint32_t)(lid & 7);            // swizzle xor (row & 7)

    // A convert/store mapping: row cr = tid/2, half ch covers 32 halves
    const int cr = tid >> 1, ch = tid & 1;
    const uint32_t crx = (uint32_t)(cr & 7);

    // aw window [t0-15, t0+79)
    for (int i = tid; i < TTILE + 2 * PAD_; i += 128) {
        int tg = t0 - PAD_ + i;
        float c0 = 0.f, c1 = 0.f;
        if (tg >= 0 && tg < T_) {
            const float* p = aw + ((size_t)b * T_ + tg) * 2;
            c0 = p[0]; c1 = p[1];
        }
        sAw[i] = c0;
        sAw[96 + i] = c1;
    }
    sPQ[tid] = g_pq[b * A_ + tid];
    sV[tid] = v[tid];
    __syncthreads();

    // -------- prologue: chunk 0 (conv) --------
    {
        unsigned char* abuf = smem + OFF_A;   // buffer 0
        float xv[8];
        #pragma unroll
        for (int j2 = 0; j2 < 4; ++j2) {
            #pragma unroll
            for (int e = 0; e < 8; ++e) {
                int j = ch * 32 + j2 * 8 + e;
                float x = 0.f;
                if (j < 62) {
                    int c = (j >= 31);
                    x = sAw[c * 96 + cr + (j - c * 31)];
                }
                xv[e] = x;
            }
            uint4 H, L;
            split2(xv[0], xv[1], H.x, L.x);
            split2(xv[2], xv[3], H.y, L.y);
            split2(xv[4], xv[5], H.z, L.z);
            split2(xv[6], xv[7], H.w, L.w);
            uint32_t c = (uint32_t)(ch * 4 + j2);
            uint32_t dst = (uint32_t)(cr << 7) + (((c ^ crx) & 7u) << 4);
            *(uint4*)(abuf + dst) = H;
            *(uint4*)(abuf + 8192 + dst) = L;
        }
        // B: Wloc hi/lo via cp.async
        #pragma unroll
        for (int it = 0; it < 8; ++it) {
            int idx = it * 128 + tid;          // 1024 (row,chunk) pairs
            uint32_t row = (uint32_t)(idx >> 3), q = (uint32_t)(idx & 7);
            uint32_t dst = sb + OFF_B + (row << 7) + (((q ^ row) & 7u) << 4);
            cp16(dst, g_WlocH + row * 64 + q * 8);
            cp16(dst + 16384, g_WlocL + row * 64 + q * 8);
        }
        cp_commit();
        cp_wait0();
    }
    __syncthreads();

    float acc[2][8][4];
    #pragma unroll
    for (int m = 0; m < 2; ++m)
        #pragma unroll
        for (int n = 0; n < 8; ++n)
            #pragma unroll
            for (int e = 0; e < 4; ++e) acc[m][n][e] = 0.f;

    // precomputed row byte offsets
    uint32_t aRowB[2], bRowB[4];
    #pragma unroll
    for (int m = 0; m < 2; ++m) aRowB[m] = (uint32_t)(tBase + m * 16 + aRowOff) << 7;
    #pragma unroll
    for (int g = 0; g < 4; ++g) bRowB[g] = (uint32_t)(aBase + g * 16 + bRowOff) << 7;

    for (int c = 0; c < NCHUNKS; ++c) {
        const uint32_t curA = sb + OFF_A + (uint32_t)(c & 1) * 16384;
        const uint32_t curB = sb + OFF_B + (uint32_t)(c & 1) * 32768;
        const bool have_next = (c + 1 < NCHUNKS);

        float4 a8[8];
        if (have_next) {
            const int kb = c * 64;   // chunk c+1 -> kbase = c*64
            const uint32_t nxtB = sb + OFF_B + (uint32_t)((c + 1) & 1) * 32768;
            const __half* WH = g_WmH + kb;
            const __half* WL = g_WmL + kb;
            #pragma unroll
            for (int it = 0; it < 8; ++it) {
                int idx = it * 128 + tid;
                uint32_t row = (uint32_t)(idx >> 3), q = (uint32_t)(idx & 7);
                uint32_t dst = nxtB + (row << 7) + (((q ^ row) & 7u) << 4);
                cp16(dst, WH + (size_t)row * E_ + q * 8);
                cp16(dst + 16384, WL + (size_t)row * E_ + q * 8);
            }
            cp_commit();
            int gt = t0 + cr;
            if (gt < T_) {
                const float* src = memory + ((size_t)b * T_ + gt) * E_ + kb + ch * 32;
                #pragma unroll
                for (int j = 0; j < 8; ++j) a8[j] = *(const float4*)(src + j * 4);
            } else {
                #pragma unroll
                for (int j = 0; j < 8; ++j) a8[j] = make_float4(0.f, 0.f, 0.f, 0.f);
            }
        }

        // ---- MMA over current chunk ----
        #pragma unroll
        for (int ks = 0; ks < 4; ++ks) {
            uint32_t ah[2][4], al[2][4];
            #pragma unroll
            for (int m = 0; m < 2; ++m) {
                uint32_t ad = curA + aRowB[m] +
                              ((((uint32_t)(2 * ks) + aCk) ^ rx) << 4);
                LDSM4(ah[m], ad);
                LDSM4(al[m], ad + 8192);
            }
            uint32_t bh[4][4], bl[4][4];
            #pragma unroll
            for (int g = 0; g < 4; ++g) {
                uint32_t bd = curB + bRowB[g] +
                              ((((uint32_t)(2 * ks) + bCk) ^ rx) << 4);
                LDSM4(bh[g], bd);
                LDSM4(bl[g], bd + 16384);
            }
            #pragma unroll
            for (int m = 0; m < 2; ++m) {
                #pragma unroll
                for (int g = 0; g < 4; ++g) {
                    MMA16816(acc[m][2 * g],     ah[m], bh[g][0], bh[g][1]);
                    MMA16816(acc[m][2 * g + 1], ah[m], bh[g][2], bh[g][3]);
                    MMA16816(acc[m][2 * g],     ah[m], bl[g][0], bl[g][1]);
                    MMA16816(acc[m][2 * g + 1], ah[m], bl[g][2], bl[g][3]);
                    MMA16816(acc[m][2 * g],     al[m], bh[g][0], bh[g][1]);
                    MMA16816(acc[m][2 * g + 1], al[m], bh[g][2], bh[g][3]);
                }
            }
        }

        if (have_next) {
            unsigned char* nb = smem + OFF_A + ((c + 1) & 1) * 16384;
            #pragma unroll
            for (int j2 = 0; j2 < 4; ++j2) {
                float4 x = a8[2 * j2], y = a8[2 * j2 + 1];
                uint4 H, L;
                split2(x.x, x.y, H.x, L.x);
                split2(x.z, x.w, H.y, L.y);
                split2(y.x, y.y, H.z, L.z);
                split2(y.z, y.w, H.w, L.w);
                uint32_t cc = (uint32_t)(ch * 4 + j2);
                uint32_t dst = (uint32_t)(cr << 7) + (((cc ^ crx) & 7u) << 4);
                *(uint4*)(nb + dst) = H;
                *(uint4*)(nb + 8192 + dst) = L;
            }
            cp_wait0();
        }
        __syncthreads();
    }

    // ---- epilogue: score[t] = sum_a v[a]*tanh(acc + pq[a]) ----
    {
        float s[4] = {0.f, 0.f, 0.f, 0.f};
        #pragma unroll
        for (int m = 0; m < 2; ++m) {
            #pragma unroll
            for (int n = 0; n < 8; ++n) {
                int a0 = aBase + n * 8 + (lid & 3) * 2;
                float v0 = sV[a0], v1 = sV[a0 + 1];
                float q0 = sPQ[a0], q1 = sPQ[a0 + 1];
                s[2 * m]     += v0 * tanhf(acc[m][n][0] + q0)
                              + v1 * tanhf(acc[m][n][1] + q1);
                s[2 * m + 1] += v0 * tanhf(acc[m][n][2] + q0)
                              + v1 * tanhf(acc[m][n][3] + q1);
            }
        }
        #pragma unroll
        for (int off = 1; off < 4; off <<= 1) {
            #pragma unroll
            for (int i = 0; i < 4; ++i)
                s[i] += __shfl_xor_sync(0xffffffffu, s[i], off);
        }
        if ((lid & 3) == 0) {
            int r = tBase + (lid >> 2);
            sSc[warpA * 64 + r]      = s[0];
            sSc[warpA * 64 + r + 8]  = s[1];
            sSc[warpA * 64 + r + 16] = s[2];
            sSc[warpA * 64 + r + 24] = s[3];
        }
    }
    __syncthreads();
    if (tid < TTILE) {
        int gt = t0 + tid;
        if (gt < T_) g_scores[b * T_ + gt] = sSc[tid] + sSc[64 + tid];
    }
}

// ---------------------------------------------------------------------------
// softmax over T per batch row (512 threads, shuffle reductions)
// ---------------------------------------------------------------------------
__global__ void softmax_kernel(float* __restrict__ align_out) {
    __shared__ float buf[T_];
    __shared__ float red[16];
    int b = blockIdx.x, tid = threadIdx.x;
    int wid = tid >> 5, lane = tid & 31;
    float mx = -1e30f;
    for (int t = tid; t < T_; t += 512) {
        float s = g_scores[b * T_ + t];
        buf[t] = s;
        mx = fmaxf(mx, s);
    }
    #pragma unroll
    for (int off = 16; off; off >>= 1)
        mx = fmaxf(mx, __shfl_xor_sync(0xffffffffu, mx, off));
    if (lane == 0) red[wid] = mx;
    __syncthreads();
    if (wid == 0) {
        float m2 = (lane < 16) ? red[lane] : -1e30f;
        #pragma unroll
        for (int off = 8; off; off >>= 1)
            m2 = fmaxf(m2, __shfl_xor_sync(0xffffffffu, m2, off));
        if (lane == 0) red[0] = m2;
    }
    __syncthreads();
    mx = red[0];
    __syncthreads();
    float sum = 0.f;
    for (int t = tid; t < T_; t += 512) {
        float e = __expf(buf[t] - mx);
        buf[t] = e;
        sum += e;
    }
    #pragma unroll
    for (int off = 16; off; off >>= 1)
        sum += __shfl_xor_sync(0xffffffffu, sum, off);
    if (lane == 0) red[wid] = sum;
    __syncthreads();
    if (wid == 0) {
        float s2 = (lane < 16) ? red[lane] : 0.f;
        #pragma unroll
        for (int off = 8; off; off >>= 1)
            s2 += __shfl_xor_sync(0xffffffffu, s2, off);
        if (lane == 0) red[0] = s2;
    }
    __syncthreads();
    float inv = 1.f / red[0];
    for (int t = tid; t < T_; t += 512) align_out[b * T_ + t] = buf[t] * inv;
}

// ---------------------------------------------------------------------------
// context partials: 25 chunks of 80 (deterministic, no atomics)
// ---------------------------------------------------------------------------
__global__ void ctx_part_kernel(const float* __restrict__ memory,
                                const float* __restrict__ aligns) {
    int chunk = blockIdx.x, b = blockIdx.y, tid = threadIdx.x;  // 128 threads
    __shared__ float sa[CLEN];
    const float* al = aligns + (size_t)b * T_ + chunk * CLEN;
    if (tid < CLEN) sa[tid] = al[tid];
    __syncthreads();
    const float* mp = memory + ((size_t)b * T_ + (size_t)chunk * CLEN) * E_ + tid * 4;
    float4 acc0 = make_float4(0.f, 0.f, 0.f, 0.f);
    float4 acc1 = make_float4(0.f, 0.f, 0.f, 0.f);
    #pragma unroll 4
    for (int tt = 0; tt < CLEN; tt += 2) {
        float a0 = sa[tt], a1 = sa[tt + 1];
        float4 m0 = *(const float4*)mp;
        float4 m1 = *(const float4*)(mp + E_);
        mp += 2 * E_;
        acc0.x += a0 * m0.x; acc0.y += a0 * m0.y;
        acc0.z += a0 * m0.z; acc0.w += a0 * m0.w;
        acc1.x += a1 * m1.x; acc1.y += a1 * m1.y;
        acc1.z += a1 * m1.z; acc1.w += a1 * m1.w;
    }
    acc0.x += acc1.x; acc0.y += acc1.y; acc0.z += acc1.z; acc0.w += acc1.w;
    *((float4*)(g_part + ((size_t)b * CCH + chunk) * E_) + tid) = acc0;
}

__global__ void ctx_reduce_kernel(float* __restrict__ ctx_out) {
    int b = blockIdx.x, e = threadIdx.x;  // 512 threads
    float s = 0.f;
    #pragma unroll
    for (int c = 0; c < CCH; ++c)
        s += g_part[((size_t)b * CCH + c) * E_ + e];
    ctx_out[b * E_ + e] = s;
}

// ---------------------------------------------------------------------------
extern "C" void kernel_launch(void* const* d_in, const int* in_sizes, int n_in,
                              void* d_out, int out_size) {
    const float* query  = (const float*)d_in[0];  // [64,1024]
    const float* memory = (const float*)d_in[1];  // [64,2000,512]
    const float* aw     = (const float*)d_in[2];  // [64,2000,2]
    const float* Wq     = (const float*)d_in[3];  // [128,1024]
    const float* Wm     = (const float*)d_in[4];  // [128,512]
    const float* Wloc   = (const float*)d_in[5];  // [128,2,31]
    const float* v      = (const float*)d_in[6];  // [128]

    float* ctx = (float*)d_out;                   // [64,512]
    float* aligns = ctx + B_ * E_;                // [64,2000]

    cudaFuncSetAttribute(scores_mma_kernel,
                         cudaFuncAttributeMaxDynamicSharedMemorySize, SMEM_TOTAL);

    prep_kernel<<<256, 256>>>(Wm, Wloc);
    pq_kernel<<<B_, 128>>>(query, Wq);
    scores_mma_kernel<<<dim3(NTILES, B_), 128, SMEM_TOTAL>>>(memory, aw, v);
    softmax_kernel<<<B_, 512>>>(aligns);
    ctx_part_kernel<<<dim3(CCH, B_), 128>>>(memory, aligns);
    ctx_reduce_kernel<<<B_, 512>>>(ctx);
}